// round 15
// baseline (speedup 1.0000x reference)
#include <cuda_runtime.h>
#include <cuda_fp16.h>
#include <cstdint>

// ============================================================================
// Problem dims
// ============================================================================
#define B_ROWS 2048
#define C_COLS 32000
#define DDIM   512
#define SCALE_F  32.0f
#define MARGIN_F 16.0f   // m * scale = 0.5 * 32

// GEMM tiling: CTA 128x256, 512 threads, 4x4 warps, warp tile 32x64
#define BM 128
#define BN 256
#define KC 64                  // K elements per chunk (64 fp16 = 128B row)
#define NCHUNK (DDIM / KC)     // 8
#define STAGES 3

#define A_TILE_B (BM * 128)    // 16384
#define W_TILE_B (BN * 128)    // 32768
#define STAGE_B  (A_TILE_B + W_TILE_B)   // 49152
#define SMEM_TOTAL (STAGES * STAGE_B)    // 147456

// Epilogue smem staging: 128 rows x 264 floats (pad vs bank conflicts)
#define EPL 264                // 128*264*4 = 135168 <= SMEM_TOTAL

// ============================================================================
// Device scratch (allocation-free rule: __device__ globals)
// ============================================================================
__device__ __half g_A[(size_t)B_ROWS * DDIM];
__device__ __half g_W[(size_t)C_COLS * DDIM];

// ============================================================================
// PTX helpers (baseline sm_80/90 ISA only — no 'a'-gated features)
// ============================================================================
__device__ __forceinline__ uint32_t smem_u32(const void* p) {
    uint32_t a;
    asm("{ .reg .u64 t; cvta.to.shared.u64 t, %1; cvt.u32.u64 %0, t; }" : "=r"(a) : "l"(p));
    return a;
}

__device__ __forceinline__ void cp16(uint32_t smem_dst, const void* gmem_src) {
    asm volatile("cp.async.cg.shared.global [%0], [%1], 16;\n"
                 :: "r"(smem_dst), "l"(__cvta_generic_to_global(gmem_src)));
}
#define CP_COMMIT() asm volatile("cp.async.commit_group;\n" ::: "memory")

__device__ __forceinline__ uint32_t sw128(uint32_t off) {
    return off ^ ((off >> 3) & 0x70);
}

__device__ __forceinline__ void ldsm_x4(uint32_t (&r)[4], uint32_t addr) {
    asm volatile("ldmatrix.sync.aligned.m8n8.x4.shared.b16 {%0,%1,%2,%3}, [%4];"
                 : "=r"(r[0]), "=r"(r[1]), "=r"(r[2]), "=r"(r[3]) : "r"(addr));
}

__device__ __forceinline__ void mma16816(float (&d)[4], const uint32_t (&a)[4],
                                         uint32_t b0, uint32_t b1) {
    asm volatile("mma.sync.aligned.m16n8k16.row.col.f32.f16.f16.f32 "
                 "{%0,%1,%2,%3}, {%4,%5,%6,%7}, {%8,%9}, {%0,%1,%2,%3};"
                 : "+f"(d[0]), "+f"(d[1]), "+f"(d[2]), "+f"(d[3])
                 : "r"(a[0]), "r"(a[1]), "r"(a[2]), "r"(a[3]), "r"(b0), "r"(b1));
}

// ============================================================================
// Kernel 1: per-row L2 norm + fp16 convert. TWO rows per warp (MLP 8).
// 256 threads = 8 warps = 16 rows per block; grid = 34048/16 = 2128.
// ============================================================================
__global__ __launch_bounds__(256) void norm_kernel(
    const float* __restrict__ x, const float* __restrict__ w)
{
    int pair = blockIdx.x * 8 + (threadIdx.x >> 5);
    int lane = threadIdx.x & 31;
    int r0 = pair * 2;

    const float* src;
    __half* dst;
    size_t row0;
    if (r0 < B_ROWS) { src = x; dst = g_A; row0 = (size_t)r0; }
    else             { src = w; dst = g_W; row0 = (size_t)(r0 - B_ROWS); }

    const float4* p0 = reinterpret_cast<const float4*>(src + row0 * DDIM);
    const float4* p1 = reinterpret_cast<const float4*>(src + (row0 + 1) * DDIM);
    float4 v0[4], v1[4];
    float s0 = 0.0f, s1 = 0.0f;
    #pragma unroll
    for (int i = 0; i < 4; i++) { v0[i] = p0[lane + 32 * i]; v1[i] = p1[lane + 32 * i]; }
    #pragma unroll
    for (int i = 0; i < 4; i++) {
        s0 += v0[i].x*v0[i].x + v0[i].y*v0[i].y + v0[i].z*v0[i].z + v0[i].w*v0[i].w;
        s1 += v1[i].x*v1[i].x + v1[i].y*v1[i].y + v1[i].z*v1[i].z + v1[i].w*v1[i].w;
    }
    #pragma unroll
    for (int o = 16; o; o >>= 1) {
        s0 += __shfl_xor_sync(0xFFFFFFFFu, s0, o);
        s1 += __shfl_xor_sync(0xFFFFFFFFu, s1, o);
    }
    float i0 = 1.0f / fmaxf(sqrtf(s0), 1e-12f);
    float i1 = 1.0f / fmaxf(sqrtf(s1), 1e-12f);

    uint2* d0 = reinterpret_cast<uint2*>(dst + row0 * DDIM);
    uint2* d1 = reinterpret_cast<uint2*>(dst + (row0 + 1) * DDIM);
    #pragma unroll
    for (int i = 0; i < 4; i++) {
        uint2 pk;
        pk.x = (uint32_t)__half_as_ushort(__float2half_rn(v0[i].x * i0))
             | ((uint32_t)__half_as_ushort(__float2half_rn(v0[i].y * i0)) << 16);
        pk.y = (uint32_t)__half_as_ushort(__float2half_rn(v0[i].z * i0))
             | ((uint32_t)__half_as_ushort(__float2half_rn(v0[i].w * i0)) << 16);
        d0[lane + 32 * i] = pk;
        pk.x = (uint32_t)__half_as_ushort(__float2half_rn(v1[i].x * i1))
             | ((uint32_t)__half_as_ushort(__float2half_rn(v1[i].y * i1)) << 16);
        pk.y = (uint32_t)__half_as_ushort(__float2half_rn(v1[i].z * i1))
             | ((uint32_t)__half_as_ushort(__float2half_rn(v1[i].w * i1)) << 16);
        d1[lane + 32 * i] = pk;
    }
}

// ============================================================================
// Kernel 2: fp16 HMMA GEMM. CTA 128x256, 512 threads / 16 warps (4x4),
// warp tile 32x64 -> acc 64 regs/thread -> ~120 total regs, 4 warps/SMSP.
// 3-stage cp.async pipeline, SW128 smem + ldmatrix. Fused margin on outL.
// ============================================================================
__global__ __launch_bounds__(512, 1)
void gemm_kernel(float* __restrict__ outL, float* __restrict__ outP,
                 const int* __restrict__ tgt)
{
    extern __shared__ char smem[];
    __shared__ int s_tcol[BM];     // target col within tile (or -1000)
    __shared__ int s_flag;         // nonzero => targets are int32-packed
    const uint32_t base = smem_u32(smem);

    const int tid  = threadIdx.x;
    const int wid  = tid >> 5;
    const int lane = tid & 31;
    const int wm   = wid >> 2;              // 0..3  (M dim)
    const int wn   = wid & 3;               // 0..3  (N dim)
    const int m0   = blockIdx.x * BM;
    const int n0   = blockIdx.y * BN;

    // ---- chunk loader: A (128x64) + W (256x64) fp16 tiles into stage s -----
    auto load_chunk = [&](int ci, int s) {
        const uint32_t sbA = base + (uint32_t)s * STAGE_B;
        const uint32_t sbW = sbA + A_TILE_B;
        const int koff = ci * KC;
        #pragma unroll
        for (int t = 0; t < 2; t++) {               // A: 1024 16B units
            int idx = tid + t * 512;
            int row = idx >> 3, c = idx & 7;
            cp16(sbA + sw128((uint32_t)(row * 128 + c * 16)),
                 g_A + (size_t)(m0 + row) * DDIM + koff + c * 8);
        }
        #pragma unroll
        for (int t = 0; t < 4; t++) {               // W: 2048 16B units
            int idx = tid + t * 512;
            int row = idx >> 3, c = idx & 7;
            cp16(sbW + sw128((uint32_t)(row * 128 + c * 16)),
                 g_W + (size_t)(n0 + row) * DDIM + koff + c * 8);
        }
        CP_COMMIT();
    };

    // Prologue: fill the pipe
    load_chunk(0, 0);
    load_chunk(1, 1);
    load_chunk(2, 2);

    // ---- targets: sniff int64 vs int32 layout, compute per-row tile col ----
    if (tid == 0) s_flag = 0;
    __syncthreads();
    if (tid < 64 && tgt[2 * tid + 1] != 0) atomicOr(&s_flag, 1);
    __syncthreads();
    if (tid < BM) {
        int t = s_flag ? tgt[m0 + tid] : tgt[2 * (m0 + tid)];
        int c = t - n0;
        s_tcol[tid] = ((unsigned)c < (unsigned)BN) ? c : -1000;
    }

    float acc[2][8][4];
    #pragma unroll
    for (int mt = 0; mt < 2; mt++)
        #pragma unroll
        for (int nt = 0; nt < 8; nt++)
            #pragma unroll
            for (int q = 0; q < 4; q++) acc[mt][nt][q] = 0.0f;

    // ldmatrix per-lane address components:
    //  A: lanes 0-15 -> rows 0-15 (k-unit = lane>>4)
    //  W: lanes 0-7 rows0-7 u0, 8-15 rows0-7 u1, 16-23 rows8-15 u0, 24-31 rows8-15 u1
    const uint32_t aRow  = (uint32_t)(wm * 32) + (lane & 15);       // + mt*16
    const uint32_t aHalf = (uint32_t)(lane >> 4);
    const uint32_t wRow  = (uint32_t)(wn * 64) + (lane & 7) + (((uint32_t)lane >> 4) << 3);
    const uint32_t wHalf = ((uint32_t)lane >> 3) & 1;

    for (int i = 0; i < NCHUNK; i++) {
        const int s = i % STAGES;
        if (i < NCHUNK - 2)       asm volatile("cp.async.wait_group 2;\n" ::: "memory");
        else if (i == NCHUNK - 2) asm volatile("cp.async.wait_group 1;\n" ::: "memory");
        else                      asm volatile("cp.async.wait_group 0;\n" ::: "memory");
        __syncthreads();

        const uint32_t sbA = base + (uint32_t)s * STAGE_B;
        const uint32_t sbW = sbA + A_TILE_B;

        #pragma unroll
        for (int kk = 0; kk < 4; kk++) {            // four k16 steps in Kc=64
            const uint32_t aU = (uint32_t)(kk * 2) + aHalf;
            const uint32_t bU = (uint32_t)(kk * 2) + wHalf;

            uint32_t a[2][4];
            #pragma unroll
            for (int mt = 0; mt < 2; mt++)
                ldsm_x4(a[mt], sbA + sw128((aRow + mt * 16) * 128 + aU * 16));

            uint32_t b[4][4];
            #pragma unroll
            for (int nt2 = 0; nt2 < 4; nt2++)
                ldsm_x4(b[nt2], sbW + sw128((wRow + nt2 * 16) * 128 + bU * 16));

            #pragma unroll
            for (int mt = 0; mt < 2; mt++)
                #pragma unroll
                for (int nt = 0; nt < 8; nt++)
                    mma16816(acc[mt][nt], a[mt],
                             b[nt >> 1][(nt & 1) * 2], b[nt >> 1][(nt & 1) * 2 + 1]);
        }

        __syncthreads();                            // all warps done reading stage s
        if (i + STAGES < NCHUNK) load_chunk(i + STAGES, s);
    }

    // ---- Epilogue: acc -> smem (scaled) -> coalesced float4 stores ---------
    __syncthreads();
    {
        float* ep = reinterpret_cast<float*>(smem);
        const int r0 = wm * 32 + (lane >> 2);       // + mt*16 (+8 for upper half)
        const int c0 = wn * 64 + (lane & 3) * 2;    // + nt*8
        #pragma unroll
        for (int mt = 0; mt < 2; mt++) {
            float* rpL = ep + (r0 + mt * 16) * EPL + c0;
            float* rpH = rpL + 8 * EPL;
            #pragma unroll
            for (int nt = 0; nt < 8; nt++) {
                *reinterpret_cast<float2*>(rpL + nt * 8) =
                    make_float2(acc[mt][nt][0] * SCALE_F, acc[mt][nt][1] * SCALE_F);
                *reinterpret_cast<float2*>(rpH + nt * 8) =
                    make_float2(acc[mt][nt][2] * SCALE_F, acc[mt][nt][3] * SCALE_F);
            }
        }
        __syncthreads();

        // Store: 128 rows x 64 float4 = 8192 float4; 16 per thread.
        #pragma unroll 4
        for (int p = 0; p < 16; p++) {
            const int idx = p * 512 + tid;
            const int r  = idx >> 6;                // /64
            const int c4 = idx & 63;
            float4 v = *reinterpret_cast<const float4*>(ep + r * EPL + c4 * 4);
            size_t o = (size_t)(m0 + r) * C_COLS + (size_t)(n0 + c4 * 4);
            *reinterpret_cast<float4*>(outP + o) = v;
            // fused margin on the loss half
            int d = s_tcol[r] - c4 * 4;
            if ((unsigned)d < 4u) {
                if (d == 0) v.x -= MARGIN_F;
                else if (d == 1) v.y -= MARGIN_F;
                else if (d == 2) v.z -= MARGIN_F;
                else v.w -= MARGIN_F;
            }
            *reinterpret_cast<float4*>(outL + o) = v;
        }
    }
}

// ============================================================================
// Launch
// ============================================================================
extern "C" void kernel_launch(void* const* d_in, const int* in_sizes, int n_in,
                              void* d_out, int out_size)
{
    (void)in_sizes; (void)n_in; (void)out_size;
    const float* x   = (const float*)d_in[0];
    const float* w   = (const float*)d_in[1];
    const int*   tgt = (const int*)d_in[2];
    float* outL = (float*)d_out;
    float* outP = outL + (size_t)B_ROWS * C_COLS;

    norm_kernel<<<(B_ROWS + C_COLS) / 16, 256>>>(x, w);

    cudaFuncSetAttribute(gemm_kernel, cudaFuncAttributeMaxDynamicSharedMemorySize, SMEM_TOTAL);
    gemm_kernel<<<dim3(B_ROWS / BM, C_COLS / BN, 1), 512, SMEM_TOTAL>>>(outL, outP, tgt);
}

// round 17
// speedup vs baseline: 1.1753x; 1.1753x over previous
#include <cuda_runtime.h>
#include <cuda_fp16.h>
#include <cstdint>

// ============================================================================
// Problem dims
// ============================================================================
#define B_ROWS 2048
#define C_COLS 32000
#define DDIM   512
#define SCALE_F  32.0f
#define MARGIN_F 16.0f   // m * scale = 0.5 * 32

// GEMM tiling: CTA 128x128, 256 threads, 4x2 warps, warp tile 32x64.
// 2 CTAs/SM (regs<=128, smem 96KB/CTA) for cross-CTA latency overlap.
#define BM 128
#define BN 128
#define KC 64                  // K elements per chunk (64 fp16 = 128B row)
#define NCHUNK (DDIM / KC)     // 8
#define STAGES 3

#define A_TILE_B (BM * 128)    // 16384
#define W_TILE_B (BN * 128)    // 16384
#define STAGE_B  (A_TILE_B + W_TILE_B)   // 32768
#define SMEM_TOTAL (STAGES * STAGE_B)    // 98304 per CTA (x2 CTAs = 196KB/SM)

// Epilogue smem staging: 128 rows x 136 floats (pad vs bank conflicts)
#define EPL 136                // 128*136*4 = 69632 <= SMEM_TOTAL

// ============================================================================
// Device scratch (allocation-free rule: __device__ globals)
// ============================================================================
__device__ __half g_A[(size_t)B_ROWS * DDIM];
__device__ __half g_W[(size_t)C_COLS * DDIM];

// ============================================================================
// PTX helpers (baseline sm_80/90 ISA only — no 'a'-gated features)
// ============================================================================
__device__ __forceinline__ uint32_t smem_u32(const void* p) {
    uint32_t a;
    asm("{ .reg .u64 t; cvta.to.shared.u64 t, %1; cvt.u32.u64 %0, t; }" : "=r"(a) : "l"(p));
    return a;
}

__device__ __forceinline__ void cp16(uint32_t smem_dst, const void* gmem_src) {
    asm volatile("cp.async.cg.shared.global [%0], [%1], 16;\n"
                 :: "r"(smem_dst), "l"(__cvta_generic_to_global(gmem_src)));
}
#define CP_COMMIT() asm volatile("cp.async.commit_group;\n" ::: "memory")

__device__ __forceinline__ uint32_t sw128(uint32_t off) {
    return off ^ ((off >> 3) & 0x70);
}

__device__ __forceinline__ void ldsm_x4(uint32_t (&r)[4], uint32_t addr) {
    asm volatile("ldmatrix.sync.aligned.m8n8.x4.shared.b16 {%0,%1,%2,%3}, [%4];"
                 : "=r"(r[0]), "=r"(r[1]), "=r"(r[2]), "=r"(r[3]) : "r"(addr));
}

__device__ __forceinline__ void mma16816(float (&d)[4], const uint32_t (&a)[4],
                                         uint32_t b0, uint32_t b1) {
    asm volatile("mma.sync.aligned.m16n8k16.row.col.f32.f16.f16.f32 "
                 "{%0,%1,%2,%3}, {%4,%5,%6,%7}, {%8,%9}, {%0,%1,%2,%3};"
                 : "+f"(d[0]), "+f"(d[1]), "+f"(d[2]), "+f"(d[3])
                 : "r"(a[0]), "r"(a[1]), "r"(a[2]), "r"(a[3]), "r"(b0), "r"(b1));
}

// ============================================================================
// Kernel 1: per-row L2 norm + fp16 convert. TWO rows per warp (MLP 8).
// 256 threads = 8 warps = 16 rows per block; grid = 34048/16 = 2128.
// ============================================================================
__global__ __launch_bounds__(256) void norm_kernel(
    const float* __restrict__ x, const float* __restrict__ w)
{
    int pair = blockIdx.x * 8 + (threadIdx.x >> 5);
    int lane = threadIdx.x & 31;
    int r0 = pair * 2;

    const float* src;
    __half* dst;
    size_t row0;
    if (r0 < B_ROWS) { src = x; dst = g_A; row0 = (size_t)r0; }
    else             { src = w; dst = g_W; row0 = (size_t)(r0 - B_ROWS); }

    const float4* p0 = reinterpret_cast<const float4*>(src + row0 * DDIM);
    const float4* p1 = reinterpret_cast<const float4*>(src + (row0 + 1) * DDIM);
    float4 v0[4], v1[4];
    float s0 = 0.0f, s1 = 0.0f;
    #pragma unroll
    for (int i = 0; i < 4; i++) { v0[i] = p0[lane + 32 * i]; v1[i] = p1[lane + 32 * i]; }
    #pragma unroll
    for (int i = 0; i < 4; i++) {
        s0 += v0[i].x*v0[i].x + v0[i].y*v0[i].y + v0[i].z*v0[i].z + v0[i].w*v0[i].w;
        s1 += v1[i].x*v1[i].x + v1[i].y*v1[i].y + v1[i].z*v1[i].z + v1[i].w*v1[i].w;
    }
    #pragma unroll
    for (int o = 16; o; o >>= 1) {
        s0 += __shfl_xor_sync(0xFFFFFFFFu, s0, o);
        s1 += __shfl_xor_sync(0xFFFFFFFFu, s1, o);
    }
    float i0 = 1.0f / fmaxf(sqrtf(s0), 1e-12f);
    float i1 = 1.0f / fmaxf(sqrtf(s1), 1e-12f);

    uint2* d0 = reinterpret_cast<uint2*>(dst + row0 * DDIM);
    uint2* d1 = reinterpret_cast<uint2*>(dst + (row0 + 1) * DDIM);
    #pragma unroll
    for (int i = 0; i < 4; i++) {
        uint2 pk;
        pk.x = (uint32_t)__half_as_ushort(__float2half_rn(v0[i].x * i0))
             | ((uint32_t)__half_as_ushort(__float2half_rn(v0[i].y * i0)) << 16);
        pk.y = (uint32_t)__half_as_ushort(__float2half_rn(v0[i].z * i0))
             | ((uint32_t)__half_as_ushort(__float2half_rn(v0[i].w * i0)) << 16);
        d0[lane + 32 * i] = pk;
        pk.x = (uint32_t)__half_as_ushort(__float2half_rn(v1[i].x * i1))
             | ((uint32_t)__half_as_ushort(__float2half_rn(v1[i].y * i1)) << 16);
        pk.y = (uint32_t)__half_as_ushort(__float2half_rn(v1[i].z * i1))
             | ((uint32_t)__half_as_ushort(__float2half_rn(v1[i].w * i1)) << 16);
        d1[lane + 32 * i] = pk;
    }
}

// ============================================================================
// Kernel 2: fp16 HMMA GEMM. CTA 128x128, 256 threads / 8 warps (4Mx2N),
// warp tile 32x64, ~123 regs -> 2 CTAs/SM. 3-stage cp.async pipeline,
// SW128 smem + ldmatrix. Fused margin on outL.
// ============================================================================
__global__ __launch_bounds__(256, 2)
void gemm_kernel(float* __restrict__ outL, float* __restrict__ outP,
                 const int* __restrict__ tgt)
{
    extern __shared__ char smem[];
    __shared__ int s_tcol[BM];     // target col within tile (or -1000)
    __shared__ int s_flag;         // nonzero => targets are int32-packed
    const uint32_t base = smem_u32(smem);

    const int tid  = threadIdx.x;
    const int wid  = tid >> 5;
    const int lane = tid & 31;
    const int wm   = wid >> 1;              // 0..3  (M dim)
    const int wn   = wid & 1;               // 0..1  (N dim)
    const int m0   = blockIdx.x * BM;
    const int n0   = blockIdx.y * BN;

    // ---- chunk loader: A (128x64) + W (128x64) fp16 tiles into stage s -----
    auto load_chunk = [&](int ci, int s) {
        const uint32_t sbA = base + (uint32_t)s * STAGE_B;
        const uint32_t sbW = sbA + A_TILE_B;
        const int koff = ci * KC;
        #pragma unroll
        for (int t = 0; t < 4; t++) {               // A: 1024 16B units
            int idx = tid + t * 256;
            int row = idx >> 3, c = idx & 7;
            cp16(sbA + sw128((uint32_t)(row * 128 + c * 16)),
                 g_A + (size_t)(m0 + row) * DDIM + koff + c * 8);
        }
        #pragma unroll
        for (int t = 0; t < 4; t++) {               // W: 1024 16B units
            int idx = tid + t * 256;
            int row = idx >> 3, c = idx & 7;
            cp16(sbW + sw128((uint32_t)(row * 128 + c * 16)),
                 g_W + (size_t)(n0 + row) * DDIM + koff + c * 8);
        }
        CP_COMMIT();
    };

    // Prologue: fill the pipe
    load_chunk(0, 0);
    load_chunk(1, 1);
    load_chunk(2, 2);

    // ---- targets: sniff int64 vs int32 layout, compute per-row tile col ----
    if (tid == 0) s_flag = 0;
    __syncthreads();
    if (tid < 64 && tgt[2 * tid + 1] != 0) atomicOr(&s_flag, 1);
    __syncthreads();
    if (tid < BM) {
        int t = s_flag ? tgt[m0 + tid] : tgt[2 * (m0 + tid)];
        int c = t - n0;
        s_tcol[tid] = ((unsigned)c < (unsigned)BN) ? c : -1000;
    }

    float acc[2][8][4];
    #pragma unroll
    for (int mt = 0; mt < 2; mt++)
        #pragma unroll
        for (int nt = 0; nt < 8; nt++)
            #pragma unroll
            for (int q = 0; q < 4; q++) acc[mt][nt][q] = 0.0f;

    // ldmatrix per-lane address components:
    //  A: lanes 0-15 -> rows 0-15 (k-unit = lane>>4)
    //  W: lanes 0-7 rows0-7 u0, 8-15 rows0-7 u1, 16-23 rows8-15 u0, 24-31 rows8-15 u1
    const uint32_t aRow  = (uint32_t)(wm * 32) + (lane & 15);       // + mt*16
    const uint32_t aHalf = (uint32_t)(lane >> 4);
    const uint32_t wRow  = (uint32_t)(wn * 64) + (lane & 7) + (((uint32_t)lane >> 4) << 3);
    const uint32_t wHalf = ((uint32_t)lane >> 3) & 1;

    for (int i = 0; i < NCHUNK; i++) {
        const int s = i % STAGES;
        if (i < NCHUNK - 2)       asm volatile("cp.async.wait_group 2;\n" ::: "memory");
        else if (i == NCHUNK - 2) asm volatile("cp.async.wait_group 1;\n" ::: "memory");
        else                      asm volatile("cp.async.wait_group 0;\n" ::: "memory");
        __syncthreads();

        const uint32_t sbA = base + (uint32_t)s * STAGE_B;
        const uint32_t sbW = sbA + A_TILE_B;

        #pragma unroll
        for (int kk = 0; kk < 4; kk++) {            // four k16 steps in Kc=64
            const uint32_t aU = (uint32_t)(kk * 2) + aHalf;
            const uint32_t bU = (uint32_t)(kk * 2) + wHalf;

            uint32_t a[2][4];
            #pragma unroll
            for (int mt = 0; mt < 2; mt++)
                ldsm_x4(a[mt], sbA + sw128((aRow + mt * 16) * 128 + aU * 16));

            uint32_t b[4][4];
            #pragma unroll
            for (int nt2 = 0; nt2 < 4; nt2++)
                ldsm_x4(b[nt2], sbW + sw128((wRow + nt2 * 16) * 128 + bU * 16));

            #pragma unroll
            for (int mt = 0; mt < 2; mt++)
                #pragma unroll
                for (int nt = 0; nt < 8; nt++)
                    mma16816(acc[mt][nt], a[mt],
                             b[nt >> 1][(nt & 1) * 2], b[nt >> 1][(nt & 1) * 2 + 1]);
        }

        __syncthreads();                            // all warps done reading stage s
        if (i + STAGES < NCHUNK) load_chunk(i + STAGES, s);
    }

    // ---- Epilogue: acc -> smem (scaled) -> coalesced float4 stores ---------
    __syncthreads();
    {
        float* ep = reinterpret_cast<float*>(smem);
        const int r0 = wm * 32 + (lane >> 2);       // + mt*16 (+8 for upper half)
        const int c0 = wn * 64 + (lane & 3) * 2;    // + nt*8
        #pragma unroll
        for (int mt = 0; mt < 2; mt++) {
            float* rpL = ep + (r0 + mt * 16) * EPL + c0;
            float* rpH = rpL + 8 * EPL;
            #pragma unroll
            for (int nt = 0; nt < 8; nt++) {
                *reinterpret_cast<float2*>(rpL + nt * 8) =
                    make_float2(acc[mt][nt][0] * SCALE_F, acc[mt][nt][1] * SCALE_F);
                *reinterpret_cast<float2*>(rpH + nt * 8) =
                    make_float2(acc[mt][nt][2] * SCALE_F, acc[mt][nt][3] * SCALE_F);
            }
        }
        __syncthreads();

        // Store: 128 rows x 32 float4 = 4096 float4; 16 per thread.
        #pragma unroll 4
        for (int p = 0; p < 16; p++) {
            const int idx = p * 256 + tid;
            const int r  = idx >> 5;                // /32
            const int c4 = idx & 31;
            float4 v = *reinterpret_cast<const float4*>(ep + r * EPL + c4 * 4);
            size_t o = (size_t)(m0 + r) * C_COLS + (size_t)(n0 + c4 * 4);
            *reinterpret_cast<float4*>(outP + o) = v;
            // fused margin on the loss half
            int d = s_tcol[r] - c4 * 4;
            if ((unsigned)d < 4u) {
                if (d == 0) v.x -= MARGIN_F;
                else if (d == 1) v.y -= MARGIN_F;
                else if (d == 2) v.z -= MARGIN_F;
                else v.w -= MARGIN_F;
            }
            *reinterpret_cast<float4*>(outL + o) = v;
        }
    }
}

// ============================================================================
// Launch
// ============================================================================
extern "C" void kernel_launch(void* const* d_in, const int* in_sizes, int n_in,
                              void* d_out, int out_size)
{
    (void)in_sizes; (void)n_in; (void)out_size;
    const float* x   = (const float*)d_in[0];
    const float* w   = (const float*)d_in[1];
    const int*   tgt = (const int*)d_in[2];
    float* outL = (float*)d_out;
    float* outP = outL + (size_t)B_ROWS * C_COLS;

    norm_kernel<<<(B_ROWS + C_COLS) / 16, 256>>>(x, w);

    cudaFuncSetAttribute(gemm_kernel, cudaFuncAttributeMaxDynamicSharedMemorySize, SMEM_TOTAL);
    gemm_kernel<<<dim3(B_ROWS / BM, C_COLS / BN, 1), 256, SMEM_TOTAL>>>(outL, outP, tgt);
}